// round 8
// baseline (speedup 1.0000x reference)
#include <cuda_runtime.h>

// ---------------------------------------------------------------------------
// Net_VIF: 6 chained quadrilinear (4D) LUT interpolations, fully fused.
// Numerics = R7 (sequential rn weight chain, fold c=0..15, packed f32x2
// mul/add per channel-pair) -> deterministic rel_err ~9.3e-4 (passes).
//
// R8: 128B-block layout + octet-cooperative XOR fetch.
//  - Each LUT repacked so the 8 corners over (b1,b2,b3) of a cell form one
//    128B line; a pixel-stage needs exactly 2 lines (b0 = 0/1).
//  - XOR load assignment: lane o, reg k loads elem o of pixel (k^o); one
//    shfl_xor(v[k], k) brings own pixel's data; a 3-level conditional-swap
//    (SEL) network de-permutes register positions. Pure bit movement.
//  - L1 work/warp-stage: 64 lines + ~63 shfl (was 128 + ~70).
// ---------------------------------------------------------------------------

#define D   17
#define D2  289
#define D3  4913
#define D4  83521
#define N_LUTS 6

typedef unsigned long long u64;

// block layout: entry = cell*8 + p, p = b1*4 + b2*2 + b3.
// 6 * 83521 * 8 * 16B = ~64 MB static device scratch (L2-resident).
__device__ __align__(128) float4 g_lutB[N_LUTS][D4 * 8];

__global__ void lut_pack_kernel(const float* __restrict__ s0, const float* __restrict__ s1,
                                const float* __restrict__ s2, const float* __restrict__ s3,
                                const float* __restrict__ s4, const float* __restrict__ s5) {
    int i = blockIdx.x * blockDim.x + threadIdx.x;
    if (i >= D4) return;
    int which = blockIdx.y;
    const float* src = (which == 0) ? s0 : (which == 1) ? s1 : (which == 2) ? s2
                     : (which == 3) ? s3 : (which == 4) ? s4 : s5;
    bool c4 = (which != 5);
    int i3 = i % D;
    int i2 = (i / D) % D;
    int i1 = (i / D2) % D;
#pragma unroll
    for (int p = 0; p < 8; ++p) {
        int b1 = p >> 2, b2 = (p >> 1) & 1, b3 = p & 1;
        float4 v = make_float4(0.0f, 0.0f, 0.0f, 0.0f);
        if ((i1 + b1) <= D - 1 && (i2 + b2) <= D - 1 && (i3 + b3) <= D - 1) {
            int o = i + b1 * D2 + b2 * D + b3;
            v.x = src[o];
            v.y = src[D4 + o];
            v.z = src[2 * D4 + o];
            v.w = c4 ? src[3 * D4 + o] : 0.0f;
        }
        g_lutB[which][i * 8 + p] = v;
    }
}

// -------- packed f32x2 helpers (same as R7) --------------------------------
__device__ __forceinline__ u64 mul2(u64 a, u64 b) {
    u64 r; asm("mul.rn.f32x2 %0, %1, %2;" : "=l"(r) : "l"(a), "l"(b)); return r;
}
__device__ __forceinline__ u64 add2(u64 a, u64 b) {
    u64 r; asm("add.rn.f32x2 %0, %1, %2;" : "=l"(r) : "l"(a), "l"(b)); return r;
}
__device__ __forceinline__ u64 packdup(float w) {
    u64 r; asm("mov.b64 %0, {%1, %2};" : "=l"(r) : "f"(w), "f"(w)); return r;
}

// corner payload: xy = channels (x,y), zw = channels (z,w)
struct C2 { u64 xy, zw; };

// Conditional swap of two corners (h uniform per lane). Pure bit movement.
__device__ __forceinline__ void cswap(C2& A, C2& B, bool h) {
    u64 axy = h ? B.xy : A.xy;  u64 bxy = h ? A.xy : B.xy;
    u64 azw = h ? B.zw : A.zw;  u64 bzw = h ? A.zw : B.zw;
    A.xy = axy; B.xy = bxy;
    A.zw = azw; B.zw = bzw;
}

__device__ __forceinline__ u64 shfl_u64(u64 v, int m) {
    return __shfl_xor_sync(0xffffffffu, v, m);
}

__device__ __forceinline__ float4 coop_stage(const float4* __restrict__ lut,
                                             float4 x, int lane) {
    const unsigned FULL = 0xffffffffu;
    const int o = lane & 7;

    // Own indices / fractions (exact ops, identical to reference).
    float t0 = __saturatef(x.x) * 16.0f;
    float t1 = __saturatef(x.y) * 16.0f;
    float t2 = __saturatef(x.z) * 16.0f;
    float t3 = __saturatef(x.w) * 16.0f;
    int i0 = min((int)t0, D - 2);
    int i1 = min((int)t1, D - 2);
    int i2 = min((int)t2, D - 2);
    int i3 = min((int)t3, D - 2);
    float f0 = t0 - (float)i0;
    float f1 = t1 - (float)i1;
    float f2 = t2 - (float)i2;
    float f3 = t3 - (float)i3;
    float g0 = 1.0f - f0, g1 = 1.0f - f1, g2 = 1.0f - f2, g3 = 1.0f - f3;
    int mybase = ((i0 * D + i1) * D + i2) * D + i3;

    // Cooperative loads with XOR assignment: lane o, reg k holds element o
    // of pixel (octet_base + (k^o)); each LDG's 32 lanes touch 4 lines.
    C2 v[8][2];
#pragma unroll
    for (int k = 0; k < 8; ++k) {
        int bk = k ? __shfl_xor_sync(FULL, mybase, k) : mybase;
        const ulonglong2 a0 = __ldg((const ulonglong2*)(lut + bk * 8 + o));
        const ulonglong2 a1 = __ldg((const ulonglong2*)(lut + (bk + D3) * 8 + o));
        v[k][0].xy = a0.x; v[k][0].zw = a0.y;
        v[k][1].xy = a1.x; v[k][1].zw = a1.y;
    }

    // One shfl_xor per register: reg k now holds own pixel's element (o^k).
#pragma unroll
    for (int k = 1; k < 8; ++k) {
#pragma unroll
        for (int j = 0; j < 2; ++j) {
            v[k][j].xy = shfl_u64(v[k][j].xy, k);
            v[k][j].zw = shfl_u64(v[k][j].zw, k);
        }
    }

    // De-permute registers by o (XOR network, levels commute):
    // after this, v[e][j] = element e (= 4*b1 + 2*b2 + b3) of own pixel.
    const bool h1 = (o & 1) != 0;
    const bool h2 = (o & 2) != 0;
    const bool h4 = (o & 4) != 0;
#pragma unroll
    for (int j = 0; j < 2; ++j) {
        cswap(v[0][j], v[1][j], h1);
        cswap(v[2][j], v[3][j], h1);
        cswap(v[4][j], v[5][j], h1);
        cswap(v[6][j], v[7][j], h1);
        cswap(v[0][j], v[2][j], h2);
        cswap(v[1][j], v[3][j], h2);
        cswap(v[4][j], v[6][j], h2);
        cswap(v[5][j], v[7][j], h2);
        cswap(v[0][j], v[4][j], h4);
        cswap(v[1][j], v[5][j], h4);
        cswap(v[2][j], v[6][j], h4);
        cswap(v[3][j], v[7][j], h4);
    }

    // Weights in the reference's exact rounding order:
    // w[c] = ((w0*w1)*w2)*w3, c = b0 | b1<<1 | b2<<2 | b3<<3.
    float p01[4];
    p01[0] = __fmul_rn(g0, g1);
    p01[1] = __fmul_rn(f0, g1);
    p01[2] = __fmul_rn(g0, f1);
    p01[3] = __fmul_rn(f0, f1);
    float p012[8];
#pragma unroll
    for (int j = 0; j < 4; ++j) {
        p012[j]     = __fmul_rn(p01[j], g2);
        p012[4 + j] = __fmul_rn(p01[j], f2);
    }
    float w[16];
#pragma unroll
    for (int j = 0; j < 8; ++j) {
        w[j]     = __fmul_rn(p012[j], g3);
        w[8 + j] = __fmul_rn(p012[j], f3);
    }

    // Sequential fold c = 0..15 (reference order), packed per channel-pair
    // exactly as R7. j = b0 = c&1; e = 4*b1 + 2*b2 + b3.
    u64 accxy = 0ull, acczw = 0ull;   // bits of (+0.0f, +0.0f)
#pragma unroll
    for (int c = 0; c < 16; ++c) {
        const int j = c & 1;
        const int e = 4 * ((c >> 1) & 1) + 2 * ((c >> 2) & 1) + ((c >> 3) & 1);
        const u64 wp = packdup(w[c]);
        accxy = add2(accxy, mul2(v[e][j].xy, wp));
        acczw = add2(acczw, mul2(v[e][j].zw, wp));
    }

    float4 r;
    asm("mov.b64 {%0, %1}, %2;" : "=f"(r.x), "=f"(r.y) : "l"(accxy));
    asm("mov.b64 {%0, %1}, %2;" : "=f"(r.z), "=f"(r.w) : "l"(acczw));
    return r;
}

__global__ void __launch_bounds__(256, 2)
net_vif_kernel(const float* __restrict__ vi,
               const float* __restrict__ ir,
               float* __restrict__ out) {
    const int HW = 512 * 512;                  // 1<<18
    int p  = blockIdx.x * blockDim.x + threadIdx.x;
    int hw = p & (HW - 1);
    int b  = p >> 18;
    int lane = threadIdx.x & 31;

    const float* vb = vi + (size_t)b * 3 * HW + hw;
    float4 x;
    x.x = vb[0];
    x.y = vb[HW];
    x.z = vb[2 * HW];
    x.w = ir[(size_t)b * HW + hw];

    x = coop_stage(g_lutB[0], x, lane);   // lut8
    x = coop_stage(g_lutB[1], x, lane);   // lut00
    x = coop_stage(g_lutB[2], x, lane);   // lut01
    x = coop_stage(g_lutB[3], x, lane);   // lut02
    x = coop_stage(g_lutB[4], x, lane);   // lut03
    x = coop_stage(g_lutB[5], x, lane);   // lutpgf (no final clip)

    float* ob = out + (size_t)b * 3 * HW + hw;
    ob[0]      = x.x;
    ob[HW]     = x.y;
    ob[2 * HW] = x.z;
}

extern "C" void kernel_launch(void* const* d_in, const int* in_sizes, int n_in,
                              void* d_out, int out_size) {
    const float* vi = (const float*)d_in[0];   // [8,3,512,512]
    const float* ir = (const float*)d_in[1];   // [8,1,512,512]

    dim3 pg((D4 + 255) / 256, N_LUTS);
    lut_pack_kernel<<<pg, 256>>>((const float*)d_in[2], (const float*)d_in[3],
                                 (const float*)d_in[4], (const float*)d_in[5],
                                 (const float*)d_in[6], (const float*)d_in[7]);

    const int total = 8 * 512 * 512;           // 2,097,152
    net_vif_kernel<<<total / 256, 256>>>(vi, ir, (float*)d_out);
}

// round 9
// speedup vs baseline: 1.7012x; 1.7012x over previous
#include <cuda_runtime.h>

// ---------------------------------------------------------------------------
// Net_VIF: 6 chained quadrilinear (4D) LUT interpolations, fully fused.
// Numerics identical (bit-for-bit) to R7/R8: sequential rn weight chain,
// fold c=0..15, packed f32x2 mul/add per channel pair.
//
// R9: 128B-block layout + ROUND-BASED octet-cooperative fetch (fixes R8):
//  - round r: all 8 lanes of an octet load pixel (octet+r)'s 128B line,
//    lane o takes element o -> each LDG touches 4 lines (64 per warp-stage,
//    half of R7's 128).
//  - 8x8 butterfly transpose (3 levels) inside the octet returns all 16
//    corners to the owning lane. Pure bit movement.
//  - pack prepass: thread per (cell, element) -> coalesced 128B stores.
// ---------------------------------------------------------------------------

#define D   17
#define D2  289
#define D3  4913
#define D4  83521
#define N_LUTS 6

typedef unsigned long long u64;

// block layout: entry = cell*8 + p, p = b1*4 + b2*2 + b3.
// 6 * 83521 * 8 * 16B = ~64 MB static device scratch (L2-resident).
__device__ __align__(128) float4 g_lutB[N_LUTS][D4 * 8];

__global__ void lut_pack_kernel(const float* __restrict__ s0, const float* __restrict__ s1,
                                const float* __restrict__ s2, const float* __restrict__ s3,
                                const float* __restrict__ s4, const float* __restrict__ s5) {
    int idx = blockIdx.x * blockDim.x + threadIdx.x;   // (cell, element)
    if (idx >= D4 * 8) return;
    int cell = idx >> 3;
    int p    = idx & 7;
    int which = blockIdx.y;
    const float* src = (which == 0) ? s0 : (which == 1) ? s1 : (which == 2) ? s2
                     : (which == 3) ? s3 : (which == 4) ? s4 : s5;
    bool c4 = (which != 5);
    int i3 = cell % D;
    int i2 = (cell / D) % D;
    int i1 = (cell / D2) % D;
    int b1 = p >> 2, b2 = (p >> 1) & 1, b3 = p & 1;
    float4 v = make_float4(0.0f, 0.0f, 0.0f, 0.0f);
    if ((i1 + b1) <= D - 1 && (i2 + b2) <= D - 1 && (i3 + b3) <= D - 1) {
        int o = cell + b1 * D2 + b2 * D + b3;
        v.x = src[o];
        v.y = src[D4 + o];
        v.z = src[2 * D4 + o];
        v.w = c4 ? src[3 * D4 + o] : 0.0f;
    }
    g_lutB[which][idx] = v;   // warp-coalesced 128B stores
}

// -------- packed f32x2 helpers (same as R7/R8) ------------------------------
__device__ __forceinline__ u64 mul2(u64 a, u64 b) {
    u64 r; asm("mul.rn.f32x2 %0, %1, %2;" : "=l"(r) : "l"(a), "l"(b)); return r;
}
__device__ __forceinline__ u64 add2(u64 a, u64 b) {
    u64 r; asm("add.rn.f32x2 %0, %1, %2;" : "=l"(r) : "l"(a), "l"(b)); return r;
}
__device__ __forceinline__ u64 packdup(float w) {
    u64 r; asm("mov.b64 %0, {%1, %2};" : "=l"(r) : "f"(w), "f"(w)); return r;
}

// corner payload: xy = channels (x,y), zw = channels (z,w)
struct C2 { u64 xy, zw; };

// One butterfly step of the cross-lane transpose (same construction that was
// bit-correct in R5's 4x4). h = (lane & m) != 0. Pure bit movement.
__device__ __forceinline__ void xstep(C2& lo, C2& hi, bool h, int m) {
    const unsigned FULL = 0xffffffffu;
    u64 s0 = h ? lo.xy : hi.xy;
    u64 s1 = h ? lo.zw : hi.zw;
    u64 r0 = __shfl_xor_sync(FULL, s0, m);
    u64 r1 = __shfl_xor_sync(FULL, s1, m);
    lo.xy = h ? r0 : lo.xy;  hi.xy = h ? hi.xy : r0;
    lo.zw = h ? r1 : lo.zw;  hi.zw = h ? hi.zw : r1;
}

__device__ __forceinline__ float4 coop_stage(const float4* __restrict__ lut,
                                             float4 x, int lane) {
    const unsigned FULL = 0xffffffffu;
    const int o = lane & 7;

    // Own indices / fractions (exact ops, identical to reference).
    float t0 = __saturatef(x.x) * 16.0f;
    float t1 = __saturatef(x.y) * 16.0f;
    float t2 = __saturatef(x.z) * 16.0f;
    float t3 = __saturatef(x.w) * 16.0f;
    int i0 = min((int)t0, D - 2);
    int i1 = min((int)t1, D - 2);
    int i2 = min((int)t2, D - 2);
    int i3 = min((int)t3, D - 2);
    float f0 = t0 - (float)i0;
    float f1 = t1 - (float)i1;
    float f2 = t2 - (float)i2;
    float f3 = t3 - (float)i3;
    float g0 = 1.0f - f0, g1 = 1.0f - f1, g2 = 1.0f - f2, g3 = 1.0f - f3;
    int mybase = ((i0 * D + i1) * D + i2) * D + i3;

    // Round-based cooperative fetch: round r serves pixel (octet + r); the
    // whole octet reads that pixel's 128B line, lane o takes element o.
    // Each LDG's 32 lanes touch exactly 4 cache lines.
    C2 v[8][2];                        // v[r][j], j = b0
#pragma unroll
    for (int r = 0; r < 8; ++r) {
        int br = __shfl_sync(FULL, mybase, r, 8);   // octet-segment broadcast
        const ulonglong2 a0 = __ldg((const ulonglong2*)(lut + br * 8 + o));
        const ulonglong2 a1 = __ldg((const ulonglong2*)(lut + (br + D3) * 8 + o));
        v[r][0].xy = a0.x; v[r][0].zw = a0.y;
        v[r][1].xy = a1.x; v[r][1].zw = a1.y;
    }

    // 8x8 butterfly transpose within the octet (levels 1, 2, 4):
    // afterwards v[e][j] = element e (= 4*b1 + 2*b2 + b3) of OWN pixel.
    const bool h1 = (o & 1) != 0;
    const bool h2 = (o & 2) != 0;
    const bool h4 = (o & 4) != 0;
#pragma unroll
    for (int j = 0; j < 2; ++j) {
        xstep(v[0][j], v[1][j], h1, 1);
        xstep(v[2][j], v[3][j], h1, 1);
        xstep(v[4][j], v[5][j], h1, 1);
        xstep(v[6][j], v[7][j], h1, 1);
        xstep(v[0][j], v[2][j], h2, 2);
        xstep(v[1][j], v[3][j], h2, 2);
        xstep(v[4][j], v[6][j], h2, 2);
        xstep(v[5][j], v[7][j], h2, 2);
        xstep(v[0][j], v[4][j], h4, 4);
        xstep(v[1][j], v[5][j], h4, 4);
        xstep(v[2][j], v[6][j], h4, 4);
        xstep(v[3][j], v[7][j], h4, 4);
    }

    // Weights in the reference's exact rounding order:
    // w[c] = ((w0*w1)*w2)*w3, c = b0 | b1<<1 | b2<<2 | b3<<3.
    float p01[4];
    p01[0] = __fmul_rn(g0, g1);
    p01[1] = __fmul_rn(f0, g1);
    p01[2] = __fmul_rn(g0, f1);
    p01[3] = __fmul_rn(f0, f1);
    float p012[8];
#pragma unroll
    for (int j = 0; j < 4; ++j) {
        p012[j]     = __fmul_rn(p01[j], g2);
        p012[4 + j] = __fmul_rn(p01[j], f2);
    }
    float w[16];
#pragma unroll
    for (int j = 0; j < 8; ++j) {
        w[j]     = __fmul_rn(p012[j], g3);
        w[8 + j] = __fmul_rn(p012[j], f3);
    }

    // Sequential fold c = 0..15 (reference order), packed per channel pair —
    // byte-identical to R7/R8. j = b0 = c&1; e = 4*b1 + 2*b2 + b3.
    u64 accxy = 0ull, acczw = 0ull;    // bits of (+0.0f, +0.0f)
#pragma unroll
    for (int c = 0; c < 16; ++c) {
        const int j = c & 1;
        const int e = 4 * ((c >> 1) & 1) + 2 * ((c >> 2) & 1) + ((c >> 3) & 1);
        const u64 wp = packdup(w[c]);
        accxy = add2(accxy, mul2(v[e][j].xy, wp));
        acczw = add2(acczw, mul2(v[e][j].zw, wp));
    }

    float4 r;
    asm("mov.b64 {%0, %1}, %2;" : "=f"(r.x), "=f"(r.y) : "l"(accxy));
    asm("mov.b64 {%0, %1}, %2;" : "=f"(r.z), "=f"(r.w) : "l"(acczw));
    return r;
}

__global__ void __launch_bounds__(256, 2)
net_vif_kernel(const float* __restrict__ vi,
               const float* __restrict__ ir,
               float* __restrict__ out) {
    const int HW = 512 * 512;                  // 1<<18
    int p  = blockIdx.x * blockDim.x + threadIdx.x;
    int hw = p & (HW - 1);
    int b  = p >> 18;
    int lane = threadIdx.x & 31;

    const float* vb = vi + (size_t)b * 3 * HW + hw;
    float4 x;
    x.x = vb[0];
    x.y = vb[HW];
    x.z = vb[2 * HW];
    x.w = ir[(size_t)b * HW + hw];

    x = coop_stage(g_lutB[0], x, lane);   // lut8
    x = coop_stage(g_lutB[1], x, lane);   // lut00
    x = coop_stage(g_lutB[2], x, lane);   // lut01
    x = coop_stage(g_lutB[3], x, lane);   // lut02
    x = coop_stage(g_lutB[4], x, lane);   // lut03
    x = coop_stage(g_lutB[5], x, lane);   // lutpgf (no final clip)

    float* ob = out + (size_t)b * 3 * HW + hw;
    ob[0]      = x.x;
    ob[HW]     = x.y;
    ob[2 * HW] = x.z;
}

extern "C" void kernel_launch(void* const* d_in, const int* in_sizes, int n_in,
                              void* d_out, int out_size) {
    const float* vi = (const float*)d_in[0];   // [8,3,512,512]
    const float* ir = (const float*)d_in[1];   // [8,1,512,512]

    dim3 pg((D4 * 8 + 255) / 256, N_LUTS);
    lut_pack_kernel<<<pg, 256>>>((const float*)d_in[2], (const float*)d_in[3],
                                 (const float*)d_in[4], (const float*)d_in[5],
                                 (const float*)d_in[6], (const float*)d_in[7]);

    const int total = 8 * 512 * 512;           // 2,097,152
    net_vif_kernel<<<total / 256, 256>>>(vi, ir, (float*)d_out);
}

// round 10
// speedup vs baseline: 2.0307x; 1.1936x over previous
#include <cuda_runtime.h>

// ---------------------------------------------------------------------------
// Net_VIF: 6 chained quadrilinear (4D) LUT interpolations, fully fused.
// Numerics bit-identical to R7/R9: sequential rn weight chain, fold c=0..15,
// packed f32x2 mul/add per channel pair (deterministic rel_err 9.274e-4).
//
// R10: 128B-block layout + 256-bit loads + quad-cooperative fetch.
//  - Blackwell ld.global.nc.v8.f32: one lane fetches 32B = 2 corners, so a
//    QUAD covers a whole 128B line -> 8 LDG.256/stage, 64 line-visits per
//    warp-stage (the delivery floor), with only the cheap 2-level 4x4
//    bundle transpose (R5's proven construction) for redistribution.
//  - combines R9's line floor with R7's cheap exchange.
// ---------------------------------------------------------------------------

#define D   17
#define D2  289
#define D3  4913
#define D4  83521
#define N_LUTS 6

typedef unsigned long long u64;

// block layout: entry = cell*8 + p, p = b1*4 + b2*2 + b3.
// 6 * 83521 * 8 * 16B = ~64 MB static device scratch (L2-resident).
__device__ __align__(128) float4 g_lutB[N_LUTS][D4 * 8];

__global__ void lut_pack_kernel(const float* __restrict__ s0, const float* __restrict__ s1,
                                const float* __restrict__ s2, const float* __restrict__ s3,
                                const float* __restrict__ s4, const float* __restrict__ s5) {
    int idx = blockIdx.x * blockDim.x + threadIdx.x;   // (cell, element)
    if (idx >= D4 * 8) return;
    int cell = idx >> 3;
    int p    = idx & 7;
    int which = blockIdx.y;
    const float* src = (which == 0) ? s0 : (which == 1) ? s1 : (which == 2) ? s2
                     : (which == 3) ? s3 : (which == 4) ? s4 : s5;
    bool c4 = (which != 5);
    int i3 = cell % D;
    int i2 = (cell / D) % D;
    int i1 = (cell / D2) % D;
    int b1 = p >> 2, b2 = (p >> 1) & 1, b3 = p & 1;
    float4 v = make_float4(0.0f, 0.0f, 0.0f, 0.0f);
    if ((i1 + b1) <= D - 1 && (i2 + b2) <= D - 1 && (i3 + b3) <= D - 1) {
        int o = cell + b1 * D2 + b2 * D + b3;
        v.x = src[o];
        v.y = src[D4 + o];
        v.z = src[2 * D4 + o];
        v.w = c4 ? src[3 * D4 + o] : 0.0f;
    }
    g_lutB[which][idx] = v;   // warp-coalesced 128B stores
}

// -------- packed f32x2 helpers (same as R7/R9) ------------------------------
__device__ __forceinline__ u64 mul2(u64 a, u64 b) {
    u64 r; asm("mul.rn.f32x2 %0, %1, %2;" : "=l"(r) : "l"(a), "l"(b)); return r;
}
__device__ __forceinline__ u64 add2(u64 a, u64 b) {
    u64 r; asm("add.rn.f32x2 %0, %1, %2;" : "=l"(r) : "l"(a), "l"(b)); return r;
}
__device__ __forceinline__ u64 packdup(float w) {
    u64 r; asm("mov.b64 %0, {%1, %2};" : "=l"(r) : "f"(w), "f"(w)); return r;
}
__device__ __forceinline__ u64 pack2(float a, float b) {
    u64 r; asm("mov.b64 %0, {%1, %2};" : "=l"(r) : "f"(a), "f"(b)); return r;
}

// corner payload: xy = channels (x,y), zw = channels (z,w)
struct C2 { u64 xy, zw; };

// One butterfly step on a 2-corner BUNDLE pair (32B each). Same construction
// as R5's bit-correct 4x4 xstep, applied to both corners of the bundle.
// h = (lane & m) != 0. Pure bit movement.
__device__ __forceinline__ void xstepB(C2 (&lo)[2], C2 (&hi)[2], bool h, int m) {
    const unsigned FULL = 0xffffffffu;
#pragma unroll
    for (int t = 0; t < 2; ++t) {
        u64 s0 = h ? lo[t].xy : hi[t].xy;
        u64 s1 = h ? lo[t].zw : hi[t].zw;
        u64 r0 = __shfl_xor_sync(FULL, s0, m);
        u64 r1 = __shfl_xor_sync(FULL, s1, m);
        lo[t].xy = h ? r0 : lo[t].xy;  hi[t].xy = h ? hi[t].xy : r0;
        lo[t].zw = h ? r1 : lo[t].zw;  hi[t].zw = h ? hi[t].zw : r1;
    }
}

__device__ __forceinline__ float4 coop_stage(const float4* __restrict__ lut,
                                             float4 x, int lane) {
    const unsigned FULL = 0xffffffffu;
    const int s = lane & 3;          // quad member

    // Own indices / fractions (exact ops, identical to reference).
    float t0 = __saturatef(x.x) * 16.0f;
    float t1 = __saturatef(x.y) * 16.0f;
    float t2 = __saturatef(x.z) * 16.0f;
    float t3 = __saturatef(x.w) * 16.0f;
    int i0 = min((int)t0, D - 2);
    int i1 = min((int)t1, D - 2);
    int i2 = min((int)t2, D - 2);
    int i3 = min((int)t3, D - 2);
    float f0 = t0 - (float)i0;
    float f1 = t1 - (float)i1;
    float f2 = t2 - (float)i2;
    float f3 = t3 - (float)i3;
    float g0 = 1.0f - f0, g1 = 1.0f - f1, g2 = 1.0f - f2, g3 = 1.0f - f3;
    int mybase = ((i0 * D + i1) * D + i2) * D + i3;

    // Quad-cooperative 256-bit fetch: round r serves pixel (quad + r); all 4
    // lanes read that pixel's 128B line, lane s takes corners {2s, 2s+1}.
    // Each LDG.256's 32 lanes touch exactly 8 cache lines.
    C2 v[2][4][2];                   // v[j][slot][half]
#pragma unroll
    for (int r = 0; r < 4; ++r) {
        int br = __shfl_sync(FULL, mybase, r, 4);   // quad-segment broadcast
#pragma unroll
        for (int j = 0; j < 2; ++j) {
            const float* p = (const float*)(lut + (size_t)(br + j * D3) * 8 + 2 * s);
            float a0, a1, a2, a3, a4, a5, a6, a7;
            asm("ld.global.nc.v8.f32 {%0,%1,%2,%3,%4,%5,%6,%7}, [%8];"
                : "=f"(a0), "=f"(a1), "=f"(a2), "=f"(a3),
                  "=f"(a4), "=f"(a5), "=f"(a6), "=f"(a7)
                : "l"(p));
            v[j][r][0].xy = pack2(a0, a1);
            v[j][r][0].zw = pack2(a2, a3);
            v[j][r][1].xy = pack2(a4, a5);
            v[j][r][1].zw = pack2(a6, a7);
        }
    }

    // 4x4 bundle transpose across quad lanes (levels 1, 2): afterwards
    // v[j][k][half] = corner p = 2k + half (p = 4*b1 + 2*b2 + b3) of OWN pixel.
    const bool h1 = (s & 1) != 0;
    const bool h2 = (s & 2) != 0;
#pragma unroll
    for (int j = 0; j < 2; ++j) {
        xstepB(v[j][0], v[j][1], h1, 1);
        xstepB(v[j][2], v[j][3], h1, 1);
        xstepB(v[j][0], v[j][2], h2, 2);
        xstepB(v[j][1], v[j][3], h2, 2);
    }

    // Weights in the reference's exact rounding order:
    // w[c] = ((w0*w1)*w2)*w3, c = b0 | b1<<1 | b2<<2 | b3<<3.
    float p01[4];
    p01[0] = __fmul_rn(g0, g1);
    p01[1] = __fmul_rn(f0, g1);
    p01[2] = __fmul_rn(g0, f1);
    p01[3] = __fmul_rn(f0, f1);
    float p012[8];
#pragma unroll
    for (int j = 0; j < 4; ++j) {
        p012[j]     = __fmul_rn(p01[j], g2);
        p012[4 + j] = __fmul_rn(p01[j], f2);
    }
    float w[16];
#pragma unroll
    for (int j = 0; j < 8; ++j) {
        w[j]     = __fmul_rn(p012[j], g3);
        w[8 + j] = __fmul_rn(p012[j], f3);
    }

    // Sequential fold c = 0..15 (reference order), packed per channel pair —
    // byte-identical to R7/R9. j = b0 = c&1; p = 4*b1 + 2*b2 + b3.
    u64 accxy = 0ull, acczw = 0ull;    // bits of (+0.0f, +0.0f)
#pragma unroll
    for (int c = 0; c < 16; ++c) {
        const int j = c & 1;
        const int p = 4 * ((c >> 1) & 1) + 2 * ((c >> 2) & 1) + ((c >> 3) & 1);
        const u64 wp = packdup(w[c]);
        const C2 vv = v[j][p >> 1][p & 1];
        accxy = add2(accxy, mul2(vv.xy, wp));
        acczw = add2(acczw, mul2(vv.zw, wp));
    }

    float4 r;
    asm("mov.b64 {%0, %1}, %2;" : "=f"(r.x), "=f"(r.y) : "l"(accxy));
    asm("mov.b64 {%0, %1}, %2;" : "=f"(r.z), "=f"(r.w) : "l"(acczw));
    return r;
}

__global__ void __launch_bounds__(256, 2)
net_vif_kernel(const float* __restrict__ vi,
               const float* __restrict__ ir,
               float* __restrict__ out) {
    const int HW = 512 * 512;                  // 1<<18
    int p  = blockIdx.x * blockDim.x + threadIdx.x;
    int hw = p & (HW - 1);
    int b  = p >> 18;
    int lane = threadIdx.x & 31;

    const float* vb = vi + (size_t)b * 3 * HW + hw;
    float4 x;
    x.x = vb[0];
    x.y = vb[HW];
    x.z = vb[2 * HW];
    x.w = ir[(size_t)b * HW + hw];

    x = coop_stage(g_lutB[0], x, lane);   // lut8
    x = coop_stage(g_lutB[1], x, lane);   // lut00
    x = coop_stage(g_lutB[2], x, lane);   // lut01
    x = coop_stage(g_lutB[3], x, lane);   // lut02
    x = coop_stage(g_lutB[4], x, lane);   // lut03
    x = coop_stage(g_lutB[5], x, lane);   // lutpgf (no final clip)

    float* ob = out + (size_t)b * 3 * HW + hw;
    ob[0]      = x.x;
    ob[HW]     = x.y;
    ob[2 * HW] = x.z;
}

extern "C" void kernel_launch(void* const* d_in, const int* in_sizes, int n_in,
                              void* d_out, int out_size) {
    const float* vi = (const float*)d_in[0];   // [8,3,512,512]
    const float* ir = (const float*)d_in[1];   // [8,1,512,512]

    dim3 pg((D4 * 8 + 255) / 256, N_LUTS);
    lut_pack_kernel<<<pg, 256>>>((const float*)d_in[2], (const float*)d_in[3],
                                 (const float*)d_in[4], (const float*)d_in[5],
                                 (const float*)d_in[6], (const float*)d_in[7]);

    const int total = 8 * 512 * 512;           // 2,097,152
    net_vif_kernel<<<total / 256, 256>>>(vi, ir, (float*)d_out);
}

// round 11
// speedup vs baseline: 2.0928x; 1.0306x over previous
#include <cuda_runtime.h>

// ---------------------------------------------------------------------------
// Net_VIF: 6 chained quadrilinear (4D) LUT interpolations, fully fused.
// Numerics: sequential rn weight chain ((w0*w1)*w2)*w3, fold c=0..15,
// packed f32x2 mul/add per channel pair (deterministic rel_err ~9.27e-4,
// stable across R7-R10 binaries).
//
// R11 = R10 (128B-block layout, LDG.256 quad-cooperative fetch, 4x4 bundle
// transpose) + occupancy push to 20 warps/SM:
//  - lazy per-corner weight generation (same rounding chain, frees ~12 regs)
//  - 128-thread blocks, __launch_bounds__(128, 5) -> 102-reg budget,
//    5 CTAs/SM = 20 warps (R10: 16 warps; R6 showed 24 is too many).
// ---------------------------------------------------------------------------

#define D   17
#define D2  289
#define D3  4913
#define D4  83521
#define N_LUTS 6

typedef unsigned long long u64;

// block layout: entry = cell*8 + p, p = b1*4 + b2*2 + b3.
// 6 * 83521 * 8 * 16B = ~64 MB static device scratch (L2-resident).
__device__ __align__(128) float4 g_lutB[N_LUTS][D4 * 8];

__global__ void lut_pack_kernel(const float* __restrict__ s0, const float* __restrict__ s1,
                                const float* __restrict__ s2, const float* __restrict__ s3,
                                const float* __restrict__ s4, const float* __restrict__ s5) {
    int idx = blockIdx.x * blockDim.x + threadIdx.x;   // (cell, element)
    if (idx >= D4 * 8) return;
    int cell = idx >> 3;
    int p    = idx & 7;
    int which = blockIdx.y;
    const float* src = (which == 0) ? s0 : (which == 1) ? s1 : (which == 2) ? s2
                     : (which == 3) ? s3 : (which == 4) ? s4 : s5;
    bool c4 = (which != 5);
    int i3 = cell % D;
    int i2 = (cell / D) % D;
    int i1 = (cell / D2) % D;
    int b1 = p >> 2, b2 = (p >> 1) & 1, b3 = p & 1;
    float4 v = make_float4(0.0f, 0.0f, 0.0f, 0.0f);
    if ((i1 + b1) <= D - 1 && (i2 + b2) <= D - 1 && (i3 + b3) <= D - 1) {
        int o = cell + b1 * D2 + b2 * D + b3;
        v.x = src[o];
        v.y = src[D4 + o];
        v.z = src[2 * D4 + o];
        v.w = c4 ? src[3 * D4 + o] : 0.0f;
    }
    g_lutB[which][idx] = v;   // warp-coalesced 128B stores
}

// -------- packed f32x2 helpers (same as R7..R10) ----------------------------
__device__ __forceinline__ u64 mul2(u64 a, u64 b) {
    u64 r; asm("mul.rn.f32x2 %0, %1, %2;" : "=l"(r) : "l"(a), "l"(b)); return r;
}
__device__ __forceinline__ u64 add2(u64 a, u64 b) {
    u64 r; asm("add.rn.f32x2 %0, %1, %2;" : "=l"(r) : "l"(a), "l"(b)); return r;
}
__device__ __forceinline__ u64 packdup(float w) {
    u64 r; asm("mov.b64 %0, {%1, %2};" : "=l"(r) : "f"(w), "f"(w)); return r;
}
__device__ __forceinline__ u64 pack2(float a, float b) {
    u64 r; asm("mov.b64 %0, {%1, %2};" : "=l"(r) : "f"(a), "f"(b)); return r;
}

// corner payload: xy = channels (x,y), zw = channels (z,w)
struct C2 { u64 xy, zw; };

// One butterfly step on a 2-corner BUNDLE pair (32B each). Bit movement only.
__device__ __forceinline__ void xstepB(C2 (&lo)[2], C2 (&hi)[2], bool h, int m) {
    const unsigned FULL = 0xffffffffu;
#pragma unroll
    for (int t = 0; t < 2; ++t) {
        u64 s0 = h ? lo[t].xy : hi[t].xy;
        u64 s1 = h ? lo[t].zw : hi[t].zw;
        u64 r0 = __shfl_xor_sync(FULL, s0, m);
        u64 r1 = __shfl_xor_sync(FULL, s1, m);
        lo[t].xy = h ? r0 : lo[t].xy;  hi[t].xy = h ? hi[t].xy : r0;
        lo[t].zw = h ? r1 : lo[t].zw;  hi[t].zw = h ? hi[t].zw : r1;
    }
}

__device__ __forceinline__ float4 coop_stage(const float4* __restrict__ lut,
                                             float4 x, int lane) {
    const unsigned FULL = 0xffffffffu;
    const int s = lane & 3;          // quad member

    // Own indices / fractions (exact ops, identical to reference).
    float t0 = __saturatef(x.x) * 16.0f;
    float t1 = __saturatef(x.y) * 16.0f;
    float t2 = __saturatef(x.z) * 16.0f;
    float t3 = __saturatef(x.w) * 16.0f;
    int i0 = min((int)t0, D - 2);
    int i1 = min((int)t1, D - 2);
    int i2 = min((int)t2, D - 2);
    int i3 = min((int)t3, D - 2);
    float f0 = t0 - (float)i0;
    float f1 = t1 - (float)i1;
    float f2 = t2 - (float)i2;
    float f3 = t3 - (float)i3;
    float g0 = 1.0f - f0, g1 = 1.0f - f1, g2 = 1.0f - f2, g3 = 1.0f - f3;
    int mybase = ((i0 * D + i1) * D + i2) * D + i3;

    // Quad-cooperative 256-bit fetch: round r serves pixel (quad + r); all 4
    // lanes read that pixel's 128B line, lane s takes corners {2s, 2s+1}.
    // Each LDG.256's 32 lanes touch exactly 8 cache lines.
    C2 v[2][4][2];                   // v[j][slot][half]
#pragma unroll
    for (int r = 0; r < 4; ++r) {
        int br = __shfl_sync(FULL, mybase, r, 4);   // quad-segment broadcast
#pragma unroll
        for (int j = 0; j < 2; ++j) {
            const float* p = (const float*)(lut + (size_t)(br + j * D3) * 8 + 2 * s);
            float a0, a1, a2, a3, a4, a5, a6, a7;
            asm("ld.global.nc.v8.f32 {%0,%1,%2,%3,%4,%5,%6,%7}, [%8];"
                : "=f"(a0), "=f"(a1), "=f"(a2), "=f"(a3),
                  "=f"(a4), "=f"(a5), "=f"(a6), "=f"(a7)
                : "l"(p));
            v[j][r][0].xy = pack2(a0, a1);
            v[j][r][0].zw = pack2(a2, a3);
            v[j][r][1].xy = pack2(a4, a5);
            v[j][r][1].zw = pack2(a6, a7);
        }
    }

    // 4x4 bundle transpose across quad lanes (levels 1, 2): afterwards
    // v[j][k][half] = corner p = 2k + half (p = 4*b1 + 2*b2 + b3) of OWN pixel.
    const bool h1 = (s & 1) != 0;
    const bool h2 = (s & 2) != 0;
#pragma unroll
    for (int j = 0; j < 2; ++j) {
        xstepB(v[j][0], v[j][1], h1, 1);
        xstepB(v[j][2], v[j][3], h1, 1);
        xstepB(v[j][0], v[j][2], h2, 2);
        xstepB(v[j][1], v[j][3], h2, 2);
    }

    // p01[j], j = b0 + 2*b1 (reference rn(w0*w1)).
    float p01[4];
    p01[0] = __fmul_rn(g0, g1);
    p01[1] = __fmul_rn(f0, g1);
    p01[2] = __fmul_rn(g0, f1);
    p01[3] = __fmul_rn(f0, f1);

    // Sequential fold c = 0..15 (reference order) with LAZY weights:
    // w = rn(rn(p01[c&3] * sel2) * sel3) — identical rounding chain to
    // ((w0*w1)*w2)*w3; selects are compile-time per unrolled c.
    // Corner: j = b0 = c&1; p = 4*b1 + 2*b2 + b3.
    u64 accxy = 0ull, acczw = 0ull;    // bits of (+0.0f, +0.0f)
#pragma unroll
    for (int c = 0; c < 16; ++c) {
        const int j = c & 1;
        const int p = 4 * ((c >> 1) & 1) + 2 * ((c >> 2) & 1) + ((c >> 3) & 1);
        const float s2 = (c & 4) ? f2 : g2;
        const float s3 = (c & 8) ? f3 : g3;
        const float wc = __fmul_rn(__fmul_rn(p01[c & 3], s2), s3);
        const u64 wp = packdup(wc);
        const C2 vv = v[j][p >> 1][p & 1];
        accxy = add2(accxy, mul2(vv.xy, wp));
        acczw = add2(acczw, mul2(vv.zw, wp));
    }

    float4 r;
    asm("mov.b64 {%0, %1}, %2;" : "=f"(r.x), "=f"(r.y) : "l"(accxy));
    asm("mov.b64 {%0, %1}, %2;" : "=f"(r.z), "=f"(r.w) : "l"(acczw));
    return r;
}

__global__ void __launch_bounds__(128, 5)
net_vif_kernel(const float* __restrict__ vi,
               const float* __restrict__ ir,
               float* __restrict__ out) {
    const int HW = 512 * 512;                  // 1<<18
    int p  = blockIdx.x * blockDim.x + threadIdx.x;
    int hw = p & (HW - 1);
    int b  = p >> 18;
    int lane = threadIdx.x & 31;

    const float* vb = vi + (size_t)b * 3 * HW + hw;
    float4 x;
    x.x = vb[0];
    x.y = vb[HW];
    x.z = vb[2 * HW];
    x.w = ir[(size_t)b * HW + hw];

    x = coop_stage(g_lutB[0], x, lane);   // lut8
    x = coop_stage(g_lutB[1], x, lane);   // lut00
    x = coop_stage(g_lutB[2], x, lane);   // lut01
    x = coop_stage(g_lutB[3], x, lane);   // lut02
    x = coop_stage(g_lutB[4], x, lane);   // lut03
    x = coop_stage(g_lutB[5], x, lane);   // lutpgf (no final clip)

    float* ob = out + (size_t)b * 3 * HW + hw;
    ob[0]      = x.x;
    ob[HW]     = x.y;
    ob[2 * HW] = x.z;
}

extern "C" void kernel_launch(void* const* d_in, const int* in_sizes, int n_in,
                              void* d_out, int out_size) {
    const float* vi = (const float*)d_in[0];   // [8,3,512,512]
    const float* ir = (const float*)d_in[1];   // [8,1,512,512]

    dim3 pg((D4 * 8 + 255) / 256, N_LUTS);
    lut_pack_kernel<<<pg, 256>>>((const float*)d_in[2], (const float*)d_in[3],
                                 (const float*)d_in[4], (const float*)d_in[5],
                                 (const float*)d_in[6], (const float*)d_in[7]);

    const int total = 8 * 512 * 512;           // 2,097,152
    net_vif_kernel<<<total / 128, 128>>>(vi, ir, (float*)d_out);
}